// round 5
// baseline (speedup 1.0000x reference)
#include <cuda_runtime.h>
#include <cstdint>

#define A_TOT 49056
#define AHALF (A_TOT/2)          // 24528 key-pair words per (b,c) plane
#define QTOT  (AHALF/4)          // 6132 uint4 per plane
#define BATCH 32
#define NFG 7
#define KTOP 200
#define NBC (BATCH*NFG)          // 224
#define NBIN 2048
#define HSHIFT 21                // bin = key32 >> 21  (exp + 2 mantissa bits)
#define CANDMAX 4096
#define NMS_THR_F 0.45f
#define LOW_SCORE_F 0.01f

// ---------------- scratch (device globals) -----------------------------------
__device__ unsigned g_k16[(size_t)NBC * AHALF];   // packed (key16 lo | key16 hi) of approx scores
__device__ unsigned g_hist[NBC * NBIN];
__device__ unsigned g_thr16[NBC];                 // 16-bit selection threshold (margin applied)
__device__ unsigned g_cand[NBC * CANDMAX];        // anchor indices
__device__ int g_ccnt[NBC];
__device__ float g_ks[NBC * KTOP];                // kept scores (sorted desc)
__device__ int   g_km[NBC * KTOP];                // kept anchors
__device__ int   g_kcnt[NBC];

// ---- exact softmax (used only on candidates; bit-exact final values) --------
__device__ __forceinline__ void softmax8(const float4 l0, const float4 l1, float* fg7) {
    float x[8] = {l0.x, l0.y, l0.z, l0.w, l1.x, l1.y, l1.z, l1.w};
    float mx = x[0];
#pragma unroll
    for (int i = 1; i < 8; i++) mx = fmaxf(mx, x[i]);
    float e[8]; float sum = 0.f;
#pragma unroll
    for (int i = 0; i < 8; i++) { e[i] = expf(x[i] - mx); sum += e[i]; }
    float inv = 1.0f / sum;
#pragma unroll
    for (int c = 0; c < NFG; c++) fg7[c] = e[c + 1] * inv;
}

// ---- fast approx softmax (selection key only; rel err <~8%) -----------------
__device__ __forceinline__ float fastexp(float x) {      // x <= 0
    x = fmaxf(x, -80.f);
    int i = __float2int_rn(fmaf(x, 12102203.0f, 1064866805.0f)); // Schraudolph
    return __int_as_float(i);
}
__device__ __forceinline__ void softmax8_fast(const float4 l0, const float4 l1, float* fg7) {
    float x[8] = {l0.x, l0.y, l0.z, l0.w, l1.x, l1.y, l1.z, l1.w};
    float mx = x[0];
#pragma unroll
    for (int i = 1; i < 8; i++) mx = fmaxf(mx, x[i]);
    float e[8]; float sum = 0.f;
#pragma unroll
    for (int i = 0; i < 8; i++) { e[i] = fastexp(x[i] - mx); sum += e[i]; }
    float inv = __fdividef(1.0f, sum);
#pragma unroll
    for (int c = 0; c < NFG; c++) fg7[c] = e[c + 1] * inv;
}

__device__ __forceinline__ float4 decode_box(float4 d, float4 db) {
    float w  = db.z - db.x,  h  = db.w - db.y;
    float cx = db.x + 0.5f * w, cy = db.y + 0.5f * h;
    float pcx = d.x / 10.0f * w + cx;
    float pcy = d.y / 10.0f * h + cy;
    float pw  = expf(d.z / 5.0f) * w;
    float ph  = expf(d.w / 5.0f) * h;
    return make_float4(
        fminf(fmaxf(pcx - 0.5f * pw, 0.f), 1.f),
        fminf(fmaxf(pcy - 0.5f * ph, 0.f), 1.f),
        fminf(fmaxf(pcx + 0.5f * pw, 0.f), 1.f),
        fminf(fmaxf(pcy + 0.5f * ph, 0.f), 1.f));
}

// ---------------- K0: zero scratch -------------------------------------------
__global__ void k_zero() {
    int i = blockIdx.x * 256 + threadIdx.x;
    if (i < NBC * NBIN) g_hist[i] = 0u;
    if (i < NBC) g_ccnt[i] = 0;
}

// ---------------- K1: fast softmax -> key16 planes + smem histogram ----------
__global__ void k_prep(const float* __restrict__ logits) {
    int b = blockIdx.x >> 4;                   // 16 chunks per image
    int chunk = blockIdx.x & 15;
    int tid = threadIdx.x;
    __shared__ unsigned hist[NFG * (NBIN / 2)]; // u16-packed halves, 28 KB
    for (int i = tid; i < NFG * (NBIN / 2); i += 256) hist[i] = 0;
    __syncthreads();

    int wbase = chunk * 1536 + tid;
#pragma unroll
    for (int k = 0; k < 6; k++) {
        int w = wbase + k * 256;
        if (w < AHALF) {
            size_t aidx = (size_t)b * A_TOT + 2 * w;
            const float4* lp = (const float4*)logits + aidx * 2;
            float4 p0 = lp[0], p1 = lp[1], p2 = lp[2], p3 = lp[3];
            float f0[NFG], f1[NFG];
            softmax8_fast(p0, p1, f0);
            softmax8_fast(p2, p3, f1);
#pragma unroll
            for (int c = 0; c < NFG; c++) {
                unsigned k0 = __float_as_uint(f0[c]);
                unsigned k1 = __float_as_uint(f1[c]);
                g_k16[(size_t)(b * NFG + c) * AHALF + w] = (k0 >> 16) | ((k1 >> 16) << 16);
                unsigned b0 = k0 >> HSHIFT, b1 = k1 >> HSHIFT;
                atomicAdd(&hist[c * (NBIN / 2) + (b0 >> 1)], 1u << ((b0 & 1) * 16));
                atomicAdd(&hist[c * (NBIN / 2) + (b1 >> 1)], 1u << ((b1 & 1) * 16));
            }
        }
    }
    __syncthreads();
    for (int i = tid; i < NFG * (NBIN / 2); i += 256) {
        unsigned v = hist[i];
        if (!v) continue;
        int c = i / (NBIN / 2), bp = i % (NBIN / 2);
        unsigned lo = v & 0xffffu, hi = v >> 16;
        unsigned* gh = &g_hist[(b * NFG + c) * NBIN + bp * 2];
        if (lo) atomicAdd(gh, lo);
        if (hi) atomicAdd(gh + 1, hi);
    }
}

// ---------------- K2: per-(b,c) threshold (with approx-error margin) ---------
__global__ void k_thr() {
    int bc = blockIdx.x;
    int tid = threadIdx.x;                      // 256 threads, 8 bins each
    const unsigned* h = g_hist + bc * NBIN;
    unsigned loc[8]; int s = 0;
    int base = tid * 8;
#pragma unroll
    for (int i = 0; i < 8; i++) { loc[i] = h[base + i]; s += (int)loc[i]; }
    __shared__ int csum[256];
    __shared__ int suf[257];
    csum[tid] = s;
    __syncthreads();
    if (tid == 0) {
        int acc = 0; suf[256] = 0;
        for (int t = 255; t >= 0; t--) { acc += csum[t]; suf[t] = acc; }
    }
    __syncthreads();
    int above = suf[tid + 1];
    if (above < KTOP && above + s >= KTOP) {
        int cum = above;
        for (int i = 7; i >= 0; i--) {
            cum += (int)loc[i];
            if (cum >= KTOP) {
                // >=200 anchors have approx score >= edge. True top-200 have
                // approx score >= 0.846*edge (8% two-sided fast-exp budget).
                float edge = __uint_as_float((unsigned)(base + i) << HSHIFT);
                g_thr16[bc] = __float_as_uint(0.80f * edge) >> 16;
                break;
            }
        }
    }
}

// ---------------- K3: candidate compaction from key16 planes -----------------
__global__ void k_sel() {
    int gt = blockIdx.x * 256 + threadIdx.x;    // 224*1536 threads total
    int plane = gt / 1536;
    int t = gt - plane * 1536;
    unsigned thr = g_thr16[plane];
    const uint4* p = (const uint4*)(g_k16 + (size_t)plane * AHALF);

    uint4 v[4];
    int cnt = 0;
#pragma unroll
    for (int j = 0; j < 4; j++) {
        int q = j * 1536 + t;
        if (q < QTOT) {
            v[j] = p[q];
            unsigned ws[4] = {v[j].x, v[j].y, v[j].z, v[j].w};
#pragma unroll
            for (int wi = 0; wi < 4; wi++) {
                cnt += ((ws[wi] & 0xffffu) >= thr);
                cnt += ((ws[wi] >> 16) >= thr);
            }
        }
    }
    // warp inclusive scan of cnt
    unsigned lane = threadIdx.x & 31;
    int incl = cnt;
#pragma unroll
    for (int d = 1; d < 32; d <<= 1) {
        int n = __shfl_up_sync(0xffffffffu, incl, d);
        if (lane >= d) incl += n;
    }
    int total = __shfl_sync(0xffffffffu, incl, 31);
    int start = 0;
    if (lane == 31 && total) start = atomicAdd(&g_ccnt[plane], total);
    start = __shfl_sync(0xffffffffu, start, 31);
    int pos = start + incl - cnt;
    if (cnt) {
#pragma unroll
        for (int j = 0; j < 4; j++) {
            int q = j * 1536 + t;
            if (q < QTOT) {
                unsigned ws[4] = {v[j].x, v[j].y, v[j].z, v[j].w};
#pragma unroll
                for (int wi = 0; wi < 4; wi++) {
                    int w = q * 4 + wi;
                    if ((ws[wi] & 0xffffu) >= thr) {
                        if (pos < CANDMAX) g_cand[plane * CANDMAX + pos] = 2 * w;
                        pos++;
                    }
                    if ((ws[wi] >> 16) >= thr) {
                        if (pos < CANDMAX) g_cand[plane * CANDMAX + pos] = 2 * w + 1;
                        pos++;
                    }
                }
            }
        }
    }
}

// ---------------- K4: exact sort + top-200 + NMS + compact -------------------
__global__ void k_nms(const float* __restrict__ logits,
                      const float* __restrict__ deltas,
                      const float* __restrict__ dbox) {
    int bc = blockIdx.x;
    int b = bc / NFG, c = bc % NFG;
    int tid = threadIdx.x;                      // 256 threads

    __shared__ unsigned long long sc[CANDMAX];  // 32 KB
    int n = g_ccnt[bc]; if (n > CANDMAX) n = CANDMAX;
    int npad = 256; while (npad < n) npad <<= 1;
    for (int i = tid; i < npad; i += 256) {
        unsigned long long e = 0ULL;
        if (i < n) {
            int a = (int)g_cand[bc * CANDMAX + i];
            const float4* lp = (const float4*)logits + ((size_t)b * A_TOT + a) * 2;
            float fg[NFG];
            softmax8(lp[0], lp[1], fg);         // EXACT values for final ordering
            unsigned key = __float_as_uint(fg[c]);
            e = ((unsigned long long)key << 32) | (unsigned)(A_TOT - a);
        }
        sc[i] = e;
    }
    __syncthreads();
    for (int k = 2; k <= npad; k <<= 1)
        for (int j = k >> 1; j > 0; j >>= 1) {
            for (int t = tid; t < npad; t += 256) {
                int l = t ^ j;
                if (l > t) {
                    bool desc = ((t & k) == 0);
                    unsigned long long va = sc[t], vb = sc[l];
                    if (desc ? (va < vb) : (va > vb)) { sc[t] = vb; sc[l] = va; }
                }
            }
            __syncthreads();
        }

    __shared__ float x0[KTOP], y0[KTOP], x1[KTOP], y1[KTOP], ar[KTOP], ss[KTOP];
    __shared__ int   an[KTOP];
    __shared__ unsigned mask[KTOP * 7];
    __shared__ unsigned remw[7];
    __shared__ int woff[8];
    if (tid < KTOP) {
        unsigned long long v = sc[tid];
        unsigned key = (unsigned)(v >> 32);
        int a = A_TOT - (int)(v & 0xffffffffu);
        float4 d  = ((const float4*)deltas)[(size_t)b * A_TOT + a];
        float4 db = ((const float4*)dbox)[a];
        float4 bx = decode_box(d, db);
        x0[tid] = bx.x; y0[tid] = bx.y; x1[tid] = bx.z; y1[tid] = bx.w;
        ar[tid] = (bx.z - bx.x) * (bx.w - bx.y);
        ss[tid] = __uint_as_float(key); an[tid] = a;
    }
    for (int i = tid; i < KTOP * 7; i += 256) mask[i] = 0;
    __syncthreads();

    for (int p = tid; p < KTOP * KTOP; p += 256) {
        int i = p / KTOP, j = p - i * KTOP;
        if (j > i) {
            float xl = fmaxf(x0[i], x0[j]);
            float yt = fmaxf(y0[i], y0[j]);
            float xr = fminf(x1[i], x1[j]);
            float yb = fminf(y1[i], y1[j]);
            float inter = fmaxf(xr - xl, 0.f) * fmaxf(yb - yt, 0.f);
            float iou = inter / (ar[i] + ar[j] - inter);   // NaN -> false (matches jax)
            if (iou > NMS_THR_F) atomicOr(&mask[i * 7 + (j >> 5)], 1u << (j & 31));
        }
    }
    __syncthreads();

    if (tid < 32) {
        unsigned rem = 0;
        if (tid < 7)
            for (int j = 0; j < 32; j++) {
                int jj = tid * 32 + j;
                if (jj < KTOP && !(ss[jj] > LOW_SCORE_F)) rem |= 1u << j;
            }
        for (int i = 0; i < KTOP; i++) {
            unsigned rw = __shfl_sync(0xffffffffu, rem, i >> 5);
            if (!((rw >> (i & 31)) & 1u))
                if (tid < 7) rem |= mask[i * 7 + tid];
        }
        if (tid < 7) remw[tid] = rem;
    }
    __syncthreads();

    if (tid == 0) {
        int s = 0;
        for (int w = 0; w < 7; w++) {
            unsigned valid = (w < 6) ? 0xffffffffu : 0xffu;   // 200 = 6*32+8
            woff[w] = s;
            s += __popc(~remw[w] & valid);
        }
        g_kcnt[bc] = s;
    }
    __syncthreads();
    if (tid < KTOP) {
        int w = tid >> 5;
        bool keep = !((remw[w] >> (tid & 31)) & 1u);
        if (keep) {
            int pos = woff[w] + __popc(~remw[w] & ((1u << (tid & 31)) - 1u));
            g_ks[bc * KTOP + pos] = ss[tid];
            g_km[bc * KTOP + pos] = an[tid];
        }
    }
}

// ---------------- K5: per-image rank-merge + decode + emit -------------------
__global__ void k_out(const float* __restrict__ deltas,
                      const float* __restrict__ dbox,
                      float* __restrict__ out) {
    int b = blockIdx.x;
    int tid = threadIdx.x;                      // 1024 threads
    __shared__ float skey[NFG * KTOP];
    __shared__ int   san[NFG * KTOP];
    __shared__ int   scnt[NFG];
    __shared__ int   total;
    if (tid < NFG) scnt[tid] = g_kcnt[b * NFG + tid];
    for (int i = tid; i < NFG * KTOP; i += 1024) {
        skey[i] = g_ks[b * NFG * KTOP + i];
        san[i]  = g_km[b * NFG * KTOP + i];
    }
    if (tid == 0) {
        int t = 0;
        for (int c = 0; c < NFG; c++) t += g_kcnt[b * NFG + c];
        total = t < KTOP ? t : KTOP;
    }
    __syncthreads();
    for (int i = total + tid; i < KTOP; i += 1024) {
        ((float4*)out)[b * KTOP + i] = make_float4(0.f, 0.f, 0.f, 0.f);
        out[BATCH * KTOP * 4 + b * KTOP + i] = 0.f;
        out[BATCH * KTOP * 5 + b * KTOP + i] = 0.f;
    }
    for (int i = tid; i < NFG * KTOP; i += 1024) {
        int c = i / KTOP, p = i - c * KTOP;
        if (p < scnt[c]) {
            float k = skey[i];
            int rank = p;
#pragma unroll
            for (int c2 = 0; c2 < NFG; c2++) {
                if (c2 == c) continue;
                int lo = 0, hi = scnt[c2];
                while (lo < hi) {
                    int mid = (lo + hi) >> 1;
                    float v = skey[c2 * KTOP + mid];
                    bool prec = (v > k) || (v == k && c2 < c);
                    if (prec) lo = mid + 1; else hi = mid;
                }
                rank += lo;
            }
            if (rank < KTOP) {
                int a = san[i];
                float4 d  = ((const float4*)deltas)[(size_t)b * A_TOT + a];
                float4 db = ((const float4*)dbox)[a];
                float4 bx = decode_box(d, db);
                ((float4*)out)[b * KTOP + rank] = bx;
                out[BATCH * KTOP * 4 + b * KTOP + rank] = k;
                out[BATCH * KTOP * 5 + b * KTOP + rank] = (float)(c + 1);
            }
        }
    }
}

// -----------------------------------------------------------------------------
extern "C" void kernel_launch(void* const* d_in, const int* in_sizes, int n_in,
                              void* d_out, int out_size) {
    const float* logits = nullptr;
    const float* deltas = nullptr;
    const float* dbox   = nullptr;
    for (int i = 0; i < n_in; i++) {
        if      (in_sizes[i] == BATCH * A_TOT * 8) logits = (const float*)d_in[i];
        else if (in_sizes[i] == BATCH * A_TOT * 4) deltas = (const float*)d_in[i];
        else if (in_sizes[i] == A_TOT * 4)         dbox   = (const float*)d_in[i];
    }
    float* out = (float*)d_out;

    k_zero<<<(NBC * NBIN + 255) / 256, 256>>>();
    k_prep<<<BATCH * 16, 256>>>(logits);
    k_thr<<<NBC, 256>>>();
    k_sel<<<(NBC * 1536) / 256, 256>>>();
    k_nms<<<NBC, 256>>>(logits, deltas, dbox);
    k_out<<<BATCH, 1024>>>(deltas, dbox, out);
}

// round 9
// speedup vs baseline: 1.0852x; 1.0852x over previous
#include <cuda_runtime.h>
#include <cstdint>

#define A_TOT 49056
#define AHALF (A_TOT/2)          // 24528 key-pair words per (b,c) plane
#define BATCH 32
#define NFG 7
#define KTOP 200
#define NBC (BATCH*NFG)          // 224
#define NBIN 2048
#define HSHIFT 21                // bin = key32 >> 21
#define NCHUNK 767               // ceil(AHALF/32) chunks of 32 words (64 anchors)
#define NCHUNKP 768
#define CANDMAX 4096
#define NMS_THR_F 0.45f
#define LOW_SCORE_F 0.01f

// ---------------- scratch (device globals) -----------------------------------
__device__ unsigned g_k16[(size_t)NBC * AHALF];        // packed (key16 lo | key16 hi)
__device__ unsigned short g_wmax[NBC * NCHUNKP];       // per-chunk max key16
__device__ unsigned g_hist[NBC * NBIN];
__device__ unsigned g_cand[NBC * CANDMAX];             // anchor indices
__device__ int g_ccnt[NBC];
__device__ float g_ks[NBC * KTOP];                     // kept scores (sorted desc)
__device__ int   g_km[NBC * KTOP];                     // kept anchors
__device__ int   g_kcnt[NBC];

// ---- exact softmax (candidates only; bit-exact final ordering) --------------
__device__ __forceinline__ void softmax8(const float4 l0, const float4 l1, float* fg7) {
    float x[8] = {l0.x, l0.y, l0.z, l0.w, l1.x, l1.y, l1.z, l1.w};
    float mx = x[0];
#pragma unroll
    for (int i = 1; i < 8; i++) mx = fmaxf(mx, x[i]);
    float e[8]; float sum = 0.f;
#pragma unroll
    for (int i = 0; i < 8; i++) { e[i] = expf(x[i] - mx); sum += e[i]; }
    float inv = 1.0f / sum;
#pragma unroll
    for (int c = 0; c < NFG; c++) fg7[c] = e[c + 1] * inv;
}

// ---- polynomial exp: no MUFU, rel err <= ~1e-5 ------------------------------
__device__ __forceinline__ float fexp(float x) {       // x <= 0
    x = fmaxf(x, -80.f);
    float t = x * 1.4426950408889634f;                 // x*log2(e)
    float r = rintf(t);
    float f = t - r;                                   // [-0.5, 0.5]
    int   i = (int)r;                                  // <= 0
    float u = f * 0.6931471805599453f;                 // f*ln2, |u|<=0.347
    float p = 1.0f + u * (1.0f + u * (0.5f + u * (0.16666667f
              + u * (0.041666667f + u * 0.0083333333f))));
    return p * __int_as_float((i + 127) << 23);
}
__device__ __forceinline__ void softmax8_fast(const float4 l0, const float4 l1, float* fg7) {
    float x[8] = {l0.x, l0.y, l0.z, l0.w, l1.x, l1.y, l1.z, l1.w};
    float mx = x[0];
#pragma unroll
    for (int i = 1; i < 8; i++) mx = fmaxf(mx, x[i]);
    float e[8]; float sum = 0.f;
#pragma unroll
    for (int i = 0; i < 8; i++) { e[i] = fexp(x[i] - mx); sum += e[i]; }
    float inv = __fdividef(1.0f, sum);
#pragma unroll
    for (int c = 0; c < NFG; c++) fg7[c] = e[c + 1] * inv;
}

__device__ __forceinline__ float4 decode_box(float4 d, float4 db) {
    float w  = db.z - db.x,  h  = db.w - db.y;
    float cx = db.x + 0.5f * w, cy = db.y + 0.5f * h;
    float pcx = d.x / 10.0f * w + cx;
    float pcy = d.y / 10.0f * h + cy;
    float pw  = expf(d.z / 5.0f) * w;
    float ph  = expf(d.w / 5.0f) * h;
    return make_float4(
        fminf(fmaxf(pcx - 0.5f * pw, 0.f), 1.f),
        fminf(fmaxf(pcy - 0.5f * ph, 0.f), 1.f),
        fminf(fmaxf(pcx + 0.5f * pw, 0.f), 1.f),
        fminf(fmaxf(pcy + 0.5f * ph, 0.f), 1.f));
}

// ---------------- K0: zero histograms ----------------------------------------
__global__ void k_zero() {
    int i = blockIdx.x * 1024 + threadIdx.x;
    if (i < NBC * NBIN / 4) ((uint4*)g_hist)[i] = make_uint4(0, 0, 0, 0);
}

// ---------------- K1: fast softmax -> keys + chunk maxima + histogram --------
__global__ void k_prep(const float* __restrict__ logits) {
    int b = blockIdx.x >> 4;                   // 16 chunks per image
    int chunk = blockIdx.x & 15;
    int tid = threadIdx.x;
    __shared__ unsigned hist[NFG * (NBIN / 2)]; // u16-packed halves, 28 KB
    for (int i = tid; i < NFG * (NBIN / 2); i += 256) hist[i] = 0;
    __syncthreads();

    int wbase = chunk * 1536 + tid;
#pragma unroll
    for (int k = 0; k < 6; k++) {
        int w = wbase + k * 256;
        bool act = w < AHALF;
        float f0[NFG], f1[NFG];
        if (act) {
            size_t aidx = (size_t)b * A_TOT + 2 * w;
            const float4* lp = (const float4*)logits + aidx * 2;
            softmax8_fast(lp[0], lp[1], f0);
            softmax8_fast(lp[2], lp[3], f1);
        }
        int cid = w >> 5;                       // uniform across warp
#pragma unroll
        for (int c = 0; c < NFG; c++) {
            unsigned k0 = 0, k1 = 0;
            if (act) {
                k0 = __float_as_uint(f0[c]);
                k1 = __float_as_uint(f1[c]);
                g_k16[(size_t)(b * NFG + c) * AHALF + w] = (k0 >> 16) | ((k1 >> 16) << 16);
                unsigned b0 = k0 >> HSHIFT, b1 = k1 >> HSHIFT;
                atomicAdd(&hist[c * (NBIN / 2) + (b0 >> 1)], 1u << ((b0 & 1) * 16));
                atomicAdd(&hist[c * (NBIN / 2) + (b1 >> 1)], 1u << ((b1 & 1) * 16));
            }
            unsigned v16 = (k0 > k1 ? k0 : k1) >> 16;
            unsigned wm = __reduce_max_sync(0xffffffffu, v16);
            if ((tid & 31) == 0)
                g_wmax[(b * NFG + c) * NCHUNKP + cid] = (unsigned short)wm;
        }
    }
    __syncthreads();
    for (int i = tid; i < NFG * (NBIN / 2); i += 256) {
        unsigned v = hist[i];
        if (!v) continue;
        int c = i / (NBIN / 2), bp = i % (NBIN / 2);
        unsigned lo = v & 0xffffu, hi = v >> 16;
        unsigned* gh = &g_hist[(b * NFG + c) * NBIN + bp * 2];
        if (lo) atomicAdd(gh, lo);
        if (hi) atomicAdd(gh + 1, hi);
    }
}

// ---------------- K2: per-plane threshold + sparse candidate compaction ------
__global__ void k_sel() {
    int bc = blockIdx.x;                        // one block per (b,c) plane
    int tid = threadIdx.x;                      // 256 threads
    int lane = tid & 31, wid = tid >> 5;

    // --- Phase A: threshold from histogram (tiny margin for poly-exp error) --
    __shared__ int csum[256];
    __shared__ int suf[257];
    __shared__ unsigned sh_thr;
    const unsigned* h = g_hist + bc * NBIN;
    unsigned loc[8]; int s = 0;
    int base = tid * 8;
#pragma unroll
    for (int i = 0; i < 8; i++) { loc[i] = h[base + i]; s += (int)loc[i]; }
    csum[tid] = s;
    __syncthreads();
    if (tid == 0) {
        int acc = 0; suf[256] = 0;
        for (int t = 255; t >= 0; t--) { acc += csum[t]; suf[t] = acc; }
    }
    __syncthreads();
    int above = suf[tid + 1];
    if (above < KTOP && above + s >= KTOP) {
        int cum = above;
        for (int i = 7; i >= 0; i--) {
            cum += (int)loc[i];
            if (cum >= KTOP) {
                float edge = __uint_as_float((unsigned)(base + i) << HSHIFT);
                sh_thr = __float_as_uint(edge * 0.9999f) >> 16;  // superset margin
                break;
            }
        }
    }
    __shared__ int hits[NCHUNKP];
    __shared__ int hcnt, ccnt;
    if (tid == 0) { hcnt = 0; ccnt = 0; }
    __syncthreads();
    unsigned thr = sh_thr;

    // --- Phase B: find chunks that can contain candidates --------------------
    const unsigned short* wmax = g_wmax + bc * NCHUNKP;
#pragma unroll
    for (int it = 0; it < 3; it++) {
        int cid = tid + it * 256;
        bool pass = (cid < NCHUNK) && ((unsigned)wmax[cid] >= thr);
        unsigned m = __ballot_sync(0xffffffffu, pass);
        if (m) {
            int bse = 0;
            if (lane == __ffs(m) - 1) bse = atomicAdd(&hcnt, __popc(m));
            bse = __shfl_sync(0xffffffffu, bse, __ffs(m) - 1);
            if (pass) hits[bse + __popc(m & ((1u << lane) - 1u))] = cid;
        }
    }
    __syncthreads();

    // --- Phase C: scan hit chunks, append candidates to smem -----------------
    __shared__ int cand[CANDMAX];               // 16 KB
    int nh = hcnt;
    const unsigned* plane = g_k16 + (size_t)bc * AHALF;
    for (int hh = wid; hh < nh; hh += 8) {
        int cid = hits[hh];
        int w = cid * 32 + lane;
        unsigned v = (w < AHALF) ? plane[w] : 0u;
        bool p0 = (v & 0xffffu) >= thr;
        bool p1 = (v >> 16) >= thr;
        unsigned m0 = __ballot_sync(0xffffffffu, p0);
        unsigned m1 = __ballot_sync(0xffffffffu, p1);
        int c0 = __popc(m0), c1 = __popc(m1);
        if (c0 + c1) {
            int bse = 0;
            if (lane == 0) bse = atomicAdd(&ccnt, c0 + c1);
            bse = __shfl_sync(0xffffffffu, bse, 0);
            unsigned below = (1u << lane) - 1u;
            if (p0) { int p = bse + __popc(m0 & below);      if (p < CANDMAX) cand[p] = 2 * w; }
            if (p1) { int p = bse + c0 + __popc(m1 & below); if (p < CANDMAX) cand[p] = 2 * w + 1; }
        }
    }
    __syncthreads();

    // --- Phase D: coalesced flush -------------------------------------------
    int n = ccnt < CANDMAX ? ccnt : CANDMAX;
    for (int i = tid; i < n; i += 256) g_cand[bc * CANDMAX + i] = (unsigned)cand[i];
    if (tid == 0) g_ccnt[bc] = n;
}

// ---------------- K3: exact sort + top-200 + NMS + compact -------------------
__global__ void k_nms(const float* __restrict__ logits,
                      const float* __restrict__ deltas,
                      const float* __restrict__ dbox) {
    int bc = blockIdx.x;
    int b = bc / NFG, c = bc % NFG;
    int tid = threadIdx.x;                      // 256 threads

    __shared__ unsigned long long sc[CANDMAX];  // 32 KB
    int n = g_ccnt[bc]; if (n > CANDMAX) n = CANDMAX;
    int npad = 256; while (npad < n) npad <<= 1;
    for (int i = tid; i < npad; i += 256) {
        unsigned long long e = 0ULL;
        if (i < n) {
            int a = (int)g_cand[bc * CANDMAX + i];
            const float4* lp = (const float4*)logits + ((size_t)b * A_TOT + a) * 2;
            float fg[NFG];
            softmax8(lp[0], lp[1], fg);         // EXACT for final ordering
            unsigned key = __float_as_uint(fg[c]);
            e = ((unsigned long long)key << 32) | (unsigned)(A_TOT - a);
        }
        sc[i] = e;
    }
    __syncthreads();
    for (int k = 2; k <= npad; k <<= 1)
        for (int j = k >> 1; j > 0; j >>= 1) {
            for (int t = tid; t < npad; t += 256) {
                int l = t ^ j;
                if (l > t) {
                    bool desc = ((t & k) == 0);
                    unsigned long long va = sc[t], vb = sc[l];
                    if (desc ? (va < vb) : (va > vb)) { sc[t] = vb; sc[l] = va; }
                }
            }
            __syncthreads();
        }

    __shared__ float x0[KTOP], y0[KTOP], x1[KTOP], y1[KTOP], ar[KTOP], ss[KTOP];
    __shared__ int   an[KTOP];
    __shared__ unsigned mask[KTOP * 7];
    __shared__ unsigned remw[7];
    __shared__ int woff[8];
    if (tid < KTOP) {
        unsigned long long v = sc[tid];
        unsigned key = (unsigned)(v >> 32);
        int a = A_TOT - (int)(v & 0xffffffffu);
        float4 d  = ((const float4*)deltas)[(size_t)b * A_TOT + a];
        float4 db = ((const float4*)dbox)[a];
        float4 bx = decode_box(d, db);
        x0[tid] = bx.x; y0[tid] = bx.y; x1[tid] = bx.z; y1[tid] = bx.w;
        ar[tid] = (bx.z - bx.x) * (bx.w - bx.y);
        ss[tid] = __uint_as_float(key); an[tid] = a;
    }
    for (int i = tid; i < KTOP * 7; i += 256) mask[i] = 0;
    __syncthreads();

    for (int p = tid; p < KTOP * KTOP; p += 256) {
        int i = p / KTOP, j = p - i * KTOP;
        if (j > i) {
            float xl = fmaxf(x0[i], x0[j]);
            float yt = fmaxf(y0[i], y0[j]);
            float xr = fminf(x1[i], x1[j]);
            float yb = fminf(y1[i], y1[j]);
            float inter = fmaxf(xr - xl, 0.f) * fmaxf(yb - yt, 0.f);
            float iou = inter / (ar[i] + ar[j] - inter);   // NaN -> false (matches jax)
            if (iou > NMS_THR_F) atomicOr(&mask[i * 7 + (j >> 5)], 1u << (j & 31));
        }
    }
    __syncthreads();

    if (tid < 32) {
        unsigned rem = 0;
        if (tid < 7)
            for (int j = 0; j < 32; j++) {
                int jj = tid * 32 + j;
                if (jj < KTOP && !(ss[jj] > LOW_SCORE_F)) rem |= 1u << j;
            }
        for (int i = 0; i < KTOP; i++) {
            unsigned rw = __shfl_sync(0xffffffffu, rem, i >> 5);
            if (!((rw >> (i & 31)) & 1u))
                if (tid < 7) rem |= mask[i * 7 + tid];
        }
        if (tid < 7) remw[tid] = rem;
    }
    __syncthreads();

    if (tid == 0) {
        int s = 0;
        for (int w = 0; w < 7; w++) {
            unsigned valid = (w < 6) ? 0xffffffffu : 0xffu;   // 200 = 6*32+8
            woff[w] = s;
            s += __popc(~remw[w] & valid);
        }
        g_kcnt[bc] = s;
    }
    __syncthreads();
    if (tid < KTOP) {
        int w = tid >> 5;
        bool keep = !((remw[w] >> (tid & 31)) & 1u);
        if (keep) {
            int pos = woff[w] + __popc(~remw[w] & ((1u << (tid & 31)) - 1u));
            g_ks[bc * KTOP + pos] = ss[tid];
            g_km[bc * KTOP + pos] = an[tid];
        }
    }
}

// ---------------- K4: per-image rank-merge + decode + emit -------------------
__global__ void k_out(const float* __restrict__ deltas,
                      const float* __restrict__ dbox,
                      float* __restrict__ out) {
    int b = blockIdx.x;
    int tid = threadIdx.x;                      // 1024 threads
    __shared__ float skey[NFG * KTOP];
    __shared__ int   san[NFG * KTOP];
    __shared__ int   scnt[NFG];
    __shared__ int   total;
    if (tid < NFG) scnt[tid] = g_kcnt[b * NFG + tid];
    for (int i = tid; i < NFG * KTOP; i += 1024) {
        skey[i] = g_ks[b * NFG * KTOP + i];
        san[i]  = g_km[b * NFG * KTOP + i];
    }
    if (tid == 0) {
        int t = 0;
        for (int c = 0; c < NFG; c++) t += g_kcnt[b * NFG + c];
        total = t < KTOP ? t : KTOP;
    }
    __syncthreads();
    for (int i = total + tid; i < KTOP; i += 1024) {
        ((float4*)out)[b * KTOP + i] = make_float4(0.f, 0.f, 0.f, 0.f);
        out[BATCH * KTOP * 4 + b * KTOP + i] = 0.f;
        out[BATCH * KTOP * 5 + b * KTOP + i] = 0.f;
    }
    for (int i = tid; i < NFG * KTOP; i += 1024) {
        int c = i / KTOP, p = i - c * KTOP;
        if (p < scnt[c]) {
            float k = skey[i];
            int rank = p;
#pragma unroll
            for (int c2 = 0; c2 < NFG; c2++) {
                if (c2 == c) continue;
                int lo = 0, hi = scnt[c2];
                while (lo < hi) {
                    int mid = (lo + hi) >> 1;
                    float v = skey[c2 * KTOP + mid];
                    bool prec = (v > k) || (v == k && c2 < c);
                    if (prec) lo = mid + 1; else hi = mid;
                }
                rank += lo;
            }
            if (rank < KTOP) {
                int a = san[i];
                float4 d  = ((const float4*)deltas)[(size_t)b * A_TOT + a];
                float4 db = ((const float4*)dbox)[a];
                float4 bx = decode_box(d, db);
                ((float4*)out)[b * KTOP + rank] = bx;
                out[BATCH * KTOP * 4 + b * KTOP + rank] = k;
                out[BATCH * KTOP * 5 + b * KTOP + rank] = (float)(c + 1);
            }
        }
    }
}

// -----------------------------------------------------------------------------
extern "C" void kernel_launch(void* const* d_in, const int* in_sizes, int n_in,
                              void* d_out, int out_size) {
    const float* logits = nullptr;
    const float* deltas = nullptr;
    const float* dbox   = nullptr;
    for (int i = 0; i < n_in; i++) {
        if      (in_sizes[i] == BATCH * A_TOT * 8) logits = (const float*)d_in[i];
        else if (in_sizes[i] == BATCH * A_TOT * 4) deltas = (const float*)d_in[i];
        else if (in_sizes[i] == A_TOT * 4)         dbox   = (const float*)d_in[i];
    }
    float* out = (float*)d_out;

    k_zero<<<(NBC * NBIN / 4 + 1023) / 1024, 1024>>>();
    k_prep<<<BATCH * 16, 256>>>(logits);
    k_sel<<<NBC, 256>>>();
    k_nms<<<NBC, 256>>>(logits, deltas, dbox);
    k_out<<<BATCH, 1024>>>(deltas, dbox, out);
}